// round 2
// baseline (speedup 1.0000x reference)
#include <cuda_runtime.h>
#include <math.h>

#define NN 50000
#define NE 600000
#define NG 256
#define BN_EPS 1e-5f
#define SB 256
#define SNB ((NN + SB - 1) / SB)   // 196 scan blocks

// ---------------- scratch (device globals) ----------------------------------
__device__ float  g_h0[(size_t)NN * 64];    // h0; later reused as layer-1 output h2 [N,64]
__device__ float  g_xl[(size_t)NN * 256];
__device__ float  g_xr[(size_t)NN * 256];
__device__ float  g_agg[(size_t)NN * 256];  // layer0 output (h1 after BN)
__device__ float  g_elog[(size_t)NE * 4];
__device__ int    g_deg[NN];
__device__ int    g_rowptr[NN + 1];
__device__ int    g_cursor[NN];
__device__ int    g_eidx[NE];
__device__ int    g_bsum[SB];
__device__ int    g_boff[SB];
__device__ double g_bns[256];
__device__ double g_bnss[256];
__device__ float  g_pool[NG * 64];
__device__ float  g_cnt[NG];

// ---------------- GEMM: C = act(A[M,K]@B[K,N] + bias) -----------------------
// 256 threads, BK=8, float4 LDS both operands.
template<int BM, int BN, int BK, int TM, int TN>
__global__ void gemm_kernel(const float* __restrict__ A, const float* __restrict__ B,
                            const float* __restrict__ bias, float* __restrict__ C,
                            int M, int N, int K, int act) {
    __shared__ float As[BK][BM];
    __shared__ float Bs[BK][BN];
    const int t = threadIdx.x;
    const int m0 = blockIdx.y * BM, n0 = blockIdx.x * BN;
    constexpr int NTX = BN / TN;
    const int tx = t % NTX, ty = t / NTX;
    float acc[TM][TN];
#pragma unroll
    for (int i = 0; i < TM; i++)
#pragma unroll
        for (int j = 0; j < TN; j++) acc[i][j] = 0.f;

    const int arow = t >> 1;           // 0..127  (BM=128, BK=8 -> 4 floats/thread)
    const int acol = (t & 1) * 4;      // 0 or 4
    constexpr int BTOT = BK * BN / 4;  // float4 loads for B tile
    const int brow = (t * 4) / BN;
    const int bcol = (t * 4) % BN;

    for (int k0 = 0; k0 < K; k0 += BK) {
        float4 av = make_float4(0.f, 0.f, 0.f, 0.f);
        if (m0 + arow < M) av = *(const float4*)(A + (size_t)(m0 + arow) * K + k0 + acol);
        As[acol + 0][arow] = av.x;
        As[acol + 1][arow] = av.y;
        As[acol + 2][arow] = av.z;
        As[acol + 3][arow] = av.w;
        if (t < BTOT) {
            float4 bv = *(const float4*)(B + (size_t)(k0 + brow) * N + n0 + bcol);
            *(float4*)&Bs[brow][bcol] = bv;
        }
        __syncthreads();
#pragma unroll
        for (int kk = 0; kk < BK; kk++) {
            float a[TM], b[TN];
#pragma unroll
            for (int i = 0; i < TM; i += 4) *(float4*)&a[i] = *(const float4*)&As[kk][ty * TM + i];
#pragma unroll
            for (int j = 0; j < TN; j += 4) *(float4*)&b[j] = *(const float4*)&Bs[kk][tx * TN + j];
#pragma unroll
            for (int i = 0; i < TM; i++)
#pragma unroll
                for (int j = 0; j < TN; j++) acc[i][j] = fmaf(a[i], b[j], acc[i][j]);
        }
        __syncthreads();
    }
#pragma unroll
    for (int i = 0; i < TM; i++) {
        int row = m0 + ty * TM + i;
        if (row >= M) continue;
#pragma unroll
        for (int j = 0; j < TN; j++) {
            int col = n0 + tx * TN + j;
            float v = acc[i][j] + bias[col];
            if (act) v = fmaxf(v, 0.f);
            C[(size_t)row * N + col] = v;
        }
    }
}

// ---------------- CSR build --------------------------------------------------
__global__ void hist_kernel(const int* __restrict__ dst, int* __restrict__ deg) {
    int e = blockIdx.x * blockDim.x + threadIdx.x;
    if (e < NE) atomicAdd(&deg[dst[e]], 1);
}

__global__ void scan_block_sums(const int* __restrict__ deg, int* __restrict__ bsum) {
    __shared__ int sh[SB];
    int i = blockIdx.x * SB + threadIdx.x;
    sh[threadIdx.x] = (i < NN) ? deg[i] : 0;
    __syncthreads();
    for (int o = SB / 2; o > 0; o >>= 1) {
        if (threadIdx.x < o) sh[threadIdx.x] += sh[threadIdx.x + o];
        __syncthreads();
    }
    if (threadIdx.x == 0) bsum[blockIdx.x] = sh[0];
}

__global__ void scan_offsets(const int* __restrict__ bsum, int* __restrict__ boff, int nb) {
    __shared__ int sh[SB];
    int t = threadIdx.x;
    int mine = (t < nb) ? bsum[t] : 0;
    sh[t] = mine;
    __syncthreads();
    for (int o = 1; o < SB; o <<= 1) {
        int v = (t >= o) ? sh[t - o] : 0;
        __syncthreads();
        sh[t] += v;
        __syncthreads();
    }
    if (t < nb) boff[t] = sh[t] - mine;  // exclusive
}

__global__ void scan_final(const int* __restrict__ deg, const int* __restrict__ boff,
                           int* __restrict__ rowptr, int* __restrict__ cursor) {
    __shared__ int sh[SB];
    int t = threadIdx.x;
    int i = blockIdx.x * SB + t;
    int d = (i < NN) ? deg[i] : 0;
    sh[t] = d;
    __syncthreads();
    for (int o = 1; o < SB; o <<= 1) {
        int v = (t >= o) ? sh[t - o] : 0;
        __syncthreads();
        sh[t] += v;
        __syncthreads();
    }
    int excl = boff[blockIdx.x] + sh[t] - d;
    if (i < NN) {
        rowptr[i] = excl;
        cursor[i] = excl;
        if (i == NN - 1) rowptr[NN] = excl + d;
    }
}

__global__ void scatter_kernel(const int* __restrict__ dst, int* __restrict__ cursor,
                               int* __restrict__ eidx) {
    int e = blockIdx.x * blockDim.x + threadIdx.x;
    if (e < NE) {
        int p = atomicAdd(&cursor[dst[e]], 1);
        eidx[p] = e;
    }
}

// ---------------- edge logits -------------------------------------------------
// warp per edge; em computed from transposed We in smem (conflict-free LDS.128),
// ea row held uniformly in all lanes' registers (no shuffles).
#define WE_S 20
__global__ void edge_logits(const float* __restrict__ xl, const float* __restrict__ xr,
                            const float* __restrict__ ea, const float* __restrict__ We,
                            const float* __restrict__ att,
                            const int* __restrict__ src, const int* __restrict__ dst,
                            float* __restrict__ elog, int E) {
    __shared__ float We_t[256 * WE_S];
    __shared__ float att_sh[256];
    const int t = threadIdx.x;
    for (int i = t; i < 4096; i += 256) {
        int f = i >> 8, c = i & 255;
        We_t[c * WE_S + f] = We[i];
    }
    if (t < 256) att_sh[t] = att[t];
    __syncthreads();

    const int lane = t & 31;
    const int e = blockIdx.x * 8 + (t >> 5);
    if (e >= E) return;
    const int s = src[e], d = dst[e];
    const float4* eap = (const float4*)(ea + (size_t)e * 16);
    float4 e0 = eap[0], e1 = eap[1], e2 = eap[2], e3 = eap[3];
    const float* xls = xl + (size_t)s * 256;
    const float* xrd = xr + (size_t)d * 256;
    float hp0 = 0.f, hp1 = 0.f, hp2 = 0.f, hp3 = 0.f;
#pragma unroll
    for (int j = 0; j < 8; j++) {
        const int c = j * 32 + lane;
        const float4* wp = (const float4*)(We_t + c * WE_S);
        float4 w0 = wp[0], w1 = wp[1], w2 = wp[2], w3 = wp[3];
        float em = e0.x * w0.x;
        em = fmaf(e0.y, w0.y, em); em = fmaf(e0.z, w0.z, em); em = fmaf(e0.w, w0.w, em);
        em = fmaf(e1.x, w1.x, em); em = fmaf(e1.y, w1.y, em); em = fmaf(e1.z, w1.z, em);
        em = fmaf(e1.w, w1.w, em); em = fmaf(e2.x, w2.x, em); em = fmaf(e2.y, w2.y, em);
        em = fmaf(e2.z, w2.z, em); em = fmaf(e2.w, w2.w, em); em = fmaf(e3.x, w3.x, em);
        em = fmaf(e3.y, w3.y, em); em = fmaf(e3.z, w3.z, em); em = fmaf(e3.w, w3.w, em);
        float z = xls[c] + xrd[c] + em;
        z = (z > 0.f) ? z : 0.2f * z;
        float p = z * att_sh[c];
        if (j < 2) hp0 += p; else if (j < 4) hp1 += p; else if (j < 6) hp2 += p; else hp3 += p;
    }
#pragma unroll
    for (int o = 16; o > 0; o >>= 1) {
        hp0 += __shfl_xor_sync(0xffffffffu, hp0, o);
        hp1 += __shfl_xor_sync(0xffffffffu, hp1, o);
        hp2 += __shfl_xor_sync(0xffffffffu, hp2, o);
        hp3 += __shfl_xor_sync(0xffffffffu, hp3, o);
    }
    if (lane < 4) {
        float v = (lane == 0) ? hp0 : (lane == 1) ? hp1 : (lane == 2) ? hp2 : hp3;
        elog[(size_t)e * 4 + lane] = v;
    }
}

// ---------------- node-centric softmax + aggregate (no atomics) --------------
__global__ void node_agg(const float* __restrict__ xl, const float* __restrict__ elog,
                         const int* __restrict__ rowptr, const int* __restrict__ eidx,
                         const int* __restrict__ srcArr, float* __restrict__ out,
                         int meanHeads) {
    const int lane = threadIdx.x & 31;
    const int d = blockIdx.x * (blockDim.x >> 5) + (threadIdx.x >> 5);
    if (d >= NN) return;
    const int start = rowptr[d];
    const int deg = rowptr[d + 1] - start;
    if (deg == 0) {
        if (meanHeads) {
            out[(size_t)d * 64 + lane] = 0.f;
            out[(size_t)d * 64 + 32 + lane] = 0.f;
        } else {
#pragma unroll
            for (int j = 0; j < 8; j++) out[(size_t)d * 256 + j * 32 + lane] = 0.f;
        }
        return;
    }
    // pass 1: per-head max
    float4 mx = make_float4(-INFINITY, -INFINITY, -INFINITY, -INFINITY);
    for (int base = 0; base < deg; base += 32) {
        int k = base + lane;
        if (k < deg) {
            float4 l = *(const float4*)(elog + (size_t)eidx[start + k] * 4);
            mx.x = fmaxf(mx.x, l.x); mx.y = fmaxf(mx.y, l.y);
            mx.z = fmaxf(mx.z, l.z); mx.w = fmaxf(mx.w, l.w);
        }
    }
#pragma unroll
    for (int o = 16; o > 0; o >>= 1) {
        mx.x = fmaxf(mx.x, __shfl_xor_sync(0xffffffffu, mx.x, o));
        mx.y = fmaxf(mx.y, __shfl_xor_sync(0xffffffffu, mx.y, o));
        mx.z = fmaxf(mx.z, __shfl_xor_sync(0xffffffffu, mx.z, o));
        mx.w = fmaxf(mx.w, __shfl_xor_sync(0xffffffffu, mx.w, o));
    }
    // pass 2: sum of exp
    float4 sm = make_float4(0.f, 0.f, 0.f, 0.f);
    for (int base = 0; base < deg; base += 32) {
        int k = base + lane;
        if (k < deg) {
            float4 l = *(const float4*)(elog + (size_t)eidx[start + k] * 4);
            sm.x += __expf(l.x - mx.x); sm.y += __expf(l.y - mx.y);
            sm.z += __expf(l.z - mx.z); sm.w += __expf(l.w - mx.w);
        }
    }
#pragma unroll
    for (int o = 16; o > 0; o >>= 1) {
        sm.x += __shfl_xor_sync(0xffffffffu, sm.x, o);
        sm.y += __shfl_xor_sync(0xffffffffu, sm.y, o);
        sm.z += __shfl_xor_sync(0xffffffffu, sm.z, o);
        sm.w += __shfl_xor_sync(0xffffffffu, sm.w, o);
    }
    float4 inv = make_float4(1.f / (sm.x + 1e-16f), 1.f / (sm.y + 1e-16f),
                             1.f / (sm.z + 1e-16f), 1.f / (sm.w + 1e-16f));
    // pass 3: alpha-weighted gather-accumulate
    float acc[8];
#pragma unroll
    for (int j = 0; j < 8; j++) acc[j] = 0.f;
    for (int base = 0; base < deg; base += 32) {
        int k = base + lane;
        int s = 0;
        float4 a = make_float4(0.f, 0.f, 0.f, 0.f);
        if (k < deg) {
            int e = eidx[start + k];
            s = srcArr[e];
            float4 l = *(const float4*)(elog + (size_t)e * 4);
            a.x = __expf(l.x - mx.x) * inv.x;
            a.y = __expf(l.y - mx.y) * inv.y;
            a.z = __expf(l.z - mx.z) * inv.z;
            a.w = __expf(l.w - mx.w) * inv.w;
        }
        int cnt = min(32, deg - base);
        for (int kk = 0; kk < cnt; kk++) {
            int ss = __shfl_sync(0xffffffffu, s, kk);
            float a0 = __shfl_sync(0xffffffffu, a.x, kk);
            float a1 = __shfl_sync(0xffffffffu, a.y, kk);
            float a2 = __shfl_sync(0xffffffffu, a.z, kk);
            float a3 = __shfl_sync(0xffffffffu, a.w, kk);
            const float* row = xl + (size_t)ss * 256;
            acc[0] = fmaf(a0, row[lane], acc[0]);
            acc[1] = fmaf(a0, row[32 + lane], acc[1]);
            acc[2] = fmaf(a1, row[64 + lane], acc[2]);
            acc[3] = fmaf(a1, row[96 + lane], acc[3]);
            acc[4] = fmaf(a2, row[128 + lane], acc[4]);
            acc[5] = fmaf(a2, row[160 + lane], acc[5]);
            acc[6] = fmaf(a3, row[192 + lane], acc[6]);
            acc[7] = fmaf(a3, row[224 + lane], acc[7]);
        }
    }
    if (meanHeads) {
        out[(size_t)d * 64 + lane] = 0.25f * (acc[0] + acc[2] + acc[4] + acc[6]);
        out[(size_t)d * 64 + 32 + lane] = 0.25f * (acc[1] + acc[3] + acc[5] + acc[7]);
    } else {
#pragma unroll
        for (int j = 0; j < 8; j++) out[(size_t)d * 256 + j * 32 + lane] = acc[j];
    }
}

// ---------------- batch norm --------------------------------------------------
__global__ void bn_stats(const float* __restrict__ h, double* __restrict__ sum,
                         double* __restrict__ sumsq, int N, int Cf, int rowsPerBlock) {
    const int t = threadIdx.x;
    const int col = t % Cf;
    const int rpb = blockDim.x / Cf;
    int r0 = blockIdx.x * rowsPerBlock;
    int rend = min(N, r0 + rowsPerBlock);
    double s = 0.0, ss = 0.0;
    for (int r = r0 + t / Cf; r < rend; r += rpb) {
        double v = (double)h[(size_t)r * Cf + col];
        s += v;
        ss += v * v;
    }
    atomicAdd(&sum[col], s);
    atomicAdd(&sumsq[col], ss);
}

__global__ void bn_apply(float* __restrict__ h, const double* __restrict__ sum,
                         const double* __restrict__ sumsq, const float* __restrict__ gamma,
                         const float* __restrict__ beta, int N, int Cf, int doRelu) {
    size_t i = (size_t)blockIdx.x * blockDim.x + threadIdx.x;
    if (i >= (size_t)N * Cf) return;
    int col = (int)(i % Cf);
    float mu = (float)(sum[col] / N);
    float var = (float)(sumsq[col] / N) - mu * mu;
    float v = gamma[col] * (h[i] - mu) * rsqrtf(var + BN_EPS) + beta[col];
    if (doRelu) v = fmaxf(v, 0.f);
    h[i] = v;
}

// ---------------- pool + MLP ---------------------------------------------------
__global__ void pool_kernel(const float* __restrict__ h, const int* __restrict__ batch,
                            float* __restrict__ pooled, float* __restrict__ cnt, int N) {
    int i = blockIdx.x * blockDim.x + threadIdx.x;
    if (i >= N * 64) return;
    int n = i >> 6, c = i & 63;
    int b = batch[n];
    atomicAdd(&pooled[b * 64 + c], h[i]);
    if (c == 0) atomicAdd(&cnt[b], 1.f);
}

__global__ void mlp_kernel(const float* __restrict__ pooled, const float* __restrict__ cnt,
                           const float* __restrict__ Wm1, const float* __restrict__ bm1,
                           const float* __restrict__ Wm2, const float* __restrict__ bm2,
                           const float* __restrict__ Wm3, const float* __restrict__ bm3,
                           float* __restrict__ out) {
    __shared__ float w1[64 * 32], w2[32 * 16], w3[16];
    int t = threadIdx.x;
    for (int i = t; i < 64 * 32; i += 256) w1[i] = Wm1[i];
    for (int i = t; i < 32 * 16; i += 256) w2[i] = Wm2[i];
    if (t < 16) w3[t] = Wm3[t];
    __syncthreads();
    float p[64];
    float c = fmaxf(cnt[t], 1.f);
#pragma unroll
    for (int f = 0; f < 64; f++) p[f] = pooled[t * 64 + f] / c;
    float z1[32];
#pragma unroll
    for (int j = 0; j < 32; j++) {
        float v = bm1[j];
#pragma unroll
        for (int f = 0; f < 64; f++) v = fmaf(p[f], w1[f * 32 + j], v);
        z1[j] = fmaxf(v, 0.f);
    }
    float z2[16];
#pragma unroll
    for (int j = 0; j < 16; j++) {
        float v = bm2[j];
#pragma unroll
        for (int f = 0; f < 32; f++) v = fmaf(z1[f], w2[f * 16 + j], v);
        z2[j] = fmaxf(v, 0.f);
    }
    float o = bm3[0];
#pragma unroll
    for (int f = 0; f < 16; f++) o = fmaf(z2[f], w3[f], o);
    out[t] = o;
}

// ---------------- launch --------------------------------------------------------
extern "C" void kernel_launch(void* const* d_in, const int* in_sizes, int n_in,
                              void* d_out, int out_size) {
    const float* f[28];
    int nf = 0, idx_ei = -1, idx_b = -1;
    for (int i = 0; i < n_in; i++) {
        if (idx_ei < 0 && in_sizes[i] == 2 * NE) { idx_ei = i; continue; }
        if (idx_b < 0 && in_sizes[i] == NN) { idx_b = i; continue; }
        if (nf < 28) f[nf++] = (const float*)d_in[i];
    }
    const float *x = f[0], *edge_attr = f[1], *W_in = f[2], *b_in = f[3];
    const float *Wl0 = f[4], *bl0 = f[5], *Wr0 = f[6], *br0 = f[7], *We0 = f[8];
    const float *att0 = f[9] /* bias0=f[10] cancels in BN */, *g0 = f[11], *beta0 = f[12];
    const float *Wl1 = f[13], *bl1 = f[14], *Wr1 = f[15], *br1 = f[16], *We1 = f[17];
    const float *att1 = f[18] /* bias1=f[19] cancels in BN */, *g1 = f[20], *beta1 = f[21];
    const float *Wm1 = f[22], *bm1 = f[23], *Wm2 = f[24], *bm2 = f[25], *Wm3 = f[26], *bm3 = f[27];
    const int* edge_index = (const int*)d_in[idx_ei];
    const int* src = edge_index;
    const int* dst = edge_index + NE;
    const int* batch = (const int*)d_in[idx_b];
    float* out = (float*)d_out;

    void *p_h0, *p_xl, *p_xr, *p_agg, *p_elog, *p_deg, *p_rowptr, *p_cursor, *p_eidx,
         *p_bsum, *p_boff, *p_bns, *p_bnss, *p_pool, *p_cnt;
    cudaGetSymbolAddress(&p_h0, g_h0);
    cudaGetSymbolAddress(&p_xl, g_xl);
    cudaGetSymbolAddress(&p_xr, g_xr);
    cudaGetSymbolAddress(&p_agg, g_agg);
    cudaGetSymbolAddress(&p_elog, g_elog);
    cudaGetSymbolAddress(&p_deg, g_deg);
    cudaGetSymbolAddress(&p_rowptr, g_rowptr);
    cudaGetSymbolAddress(&p_cursor, g_cursor);
    cudaGetSymbolAddress(&p_eidx, g_eidx);
    cudaGetSymbolAddress(&p_bsum, g_bsum);
    cudaGetSymbolAddress(&p_boff, g_boff);
    cudaGetSymbolAddress(&p_bns, g_bns);
    cudaGetSymbolAddress(&p_bnss, g_bnss);
    cudaGetSymbolAddress(&p_pool, g_pool);
    cudaGetSymbolAddress(&p_cnt, g_cnt);
    float* h0 = (float*)p_h0;
    float* xl = (float*)p_xl;
    float* xr = (float*)p_xr;
    float* agg = (float*)p_agg;
    float* elog = (float*)p_elog;
    int* deg = (int*)p_deg;
    int* rowptr = (int*)p_rowptr;
    int* cursor = (int*)p_cursor;
    int* eidx = (int*)p_eidx;
    int* bsum = (int*)p_bsum;
    int* boff = (int*)p_boff;
    double* bns = (double*)p_bns;
    double* bnss = (double*)p_bnss;
    float* pool = (float*)p_pool;
    float* cnt = (float*)p_cnt;

    const int EB = (NE + 7) / 8;     // warp-per-edge blocks (8 warps)
    const int NB = (NN + 7) / 8;     // warp-per-node blocks
    const int ROWS = 512;
    const int bnBlocks = (NN + ROWS - 1) / ROWS;

    // ---- CSR build (dst shared by both layers)
    cudaMemsetAsync(deg, 0, NN * sizeof(int));
    hist_kernel<<<(NE + 255) / 256, 256>>>(dst, deg);
    scan_block_sums<<<SNB, SB>>>(deg, bsum);
    scan_offsets<<<1, SB>>>(bsum, boff, SNB);
    scan_final<<<SNB, SB>>>(deg, boff, rowptr, cursor);
    scatter_kernel<<<(NE + 255) / 256, 256>>>(dst, cursor, eidx);

    // ---- input projection: h0 = relu(x@W_in + b_in)
    {
        dim3 g(64 / 64, (NN + 127) / 128);
        gemm_kernel<128, 64, 8, 8, 4><<<g, 256>>>(x, W_in, b_in, h0, NN, 64, 64, 1);
    }

    // ---- GATv2 layer 0
    {
        dim3 g(256 / 128, (NN + 127) / 128);
        gemm_kernel<128, 128, 8, 8, 8><<<g, 256>>>(h0, Wl0, bl0, xl, NN, 256, 64, 0);
        gemm_kernel<128, 128, 8, 8, 8><<<g, 256>>>(h0, Wr0, br0, xr, NN, 256, 64, 0);
    }
    edge_logits<<<EB, 256>>>(xl, xr, edge_attr, We0, att0, src, dst, elog, NE);
    node_agg<<<NB, 256>>>(xl, elog, rowptr, eidx, src, agg, 0);
    cudaMemsetAsync(bns, 0, 256 * sizeof(double));
    cudaMemsetAsync(bnss, 0, 256 * sizeof(double));
    bn_stats<<<bnBlocks, 256>>>(agg, bns, bnss, NN, 256, ROWS);
    bn_apply<<<(NN * 256 + 255) / 256, 256>>>(agg, bns, bnss, g0, beta0, NN, 256, 1);

    // ---- GATv2 layer 1
    {
        dim3 g(256 / 128, (NN + 127) / 128);
        gemm_kernel<128, 128, 8, 8, 8><<<g, 256>>>(agg, Wl1, bl1, xl, NN, 256, 256, 0);
        gemm_kernel<128, 128, 8, 8, 8><<<g, 256>>>(agg, Wr1, br1, xr, NN, 256, 256, 0);
    }
    edge_logits<<<EB, 256>>>(xl, xr, edge_attr, We1, att1, src, dst, elog, NE);
    node_agg<<<NB, 256>>>(xl, elog, rowptr, eidx, src, h0, 1);  // mean over heads -> h2 [N,64]
    cudaMemsetAsync(bns, 0, 256 * sizeof(double));
    cudaMemsetAsync(bnss, 0, 256 * sizeof(double));
    bn_stats<<<bnBlocks, 256>>>(h0, bns, bnss, NN, 64, ROWS);
    bn_apply<<<(NN * 64 + 255) / 256, 256>>>(h0, bns, bnss, g1, beta1, NN, 64, 0);

    // ---- global mean pool + MLP head
    cudaMemsetAsync(pool, 0, NG * 64 * sizeof(float));
    cudaMemsetAsync(cnt, 0, NG * sizeof(float));
    pool_kernel<<<(NN * 64 + 255) / 256, 256>>>(h0, batch, pool, cnt, NN);
    mlp_kernel<<<1, 256>>>(pool, cnt, Wm1, bm1, Wm2, bm2, Wm3, bm3, out);
}

// round 3
// speedup vs baseline: 1.2188x; 1.2188x over previous
#include <cuda_runtime.h>
#include <cuda_fp16.h>
#include <math.h>

#define NN 50000
#define NE 600000
#define NG 256
#define BN_EPS 1e-5f
#define SB 256
#define SNB ((NN + SB - 1) / SB)

// ---------------- scratch (device globals) ----------------------------------
__device__ float  g_h0[(size_t)NN * 64];
__device__ float  g_xl[(size_t)NN * 256];
__device__ float  g_xr[(size_t)NN * 256];
__device__ float  g_agg[(size_t)NN * 256];
__device__ __half g_em[(size_t)NE * 256];     // em = ea_perm @ We (fp16), CSR order
__device__ float  g_ea_perm[(size_t)NE * 16];
__device__ int    g_src_perm[NE];
__device__ int    g_deg[NN];
__device__ int    g_rowptr[NN + 1];
__device__ int    g_cursor[NN];
__device__ int    g_eidx[NE];
__device__ int    g_bsum[SB];
__device__ int    g_boff[SB];
__device__ double g_bns[256];
__device__ double g_bnss[256];
__device__ float  g_pool[NG * 64];
__device__ float  g_cnt[NG];

// ---------------- GEMM: C = act(A[M,K]@B[K,N] + bias) -----------------------
template<int BM, int BN, int BK, int TM, int TN, bool HALFOUT>
__global__ void gemm_kernel(const float* __restrict__ A, const float* __restrict__ B,
                            const float* __restrict__ bias, void* __restrict__ Cv,
                            int M, int N, int K, int act) {
    __shared__ float As[BK][BM];
    __shared__ float Bs[BK][BN];
    const int t = threadIdx.x;
    const int m0 = blockIdx.y * BM, n0 = blockIdx.x * BN;
    constexpr int NTX = BN / TN;
    const int tx = t % NTX, ty = t / NTX;
    float acc[TM][TN];
#pragma unroll
    for (int i = 0; i < TM; i++)
#pragma unroll
        for (int j = 0; j < TN; j++) acc[i][j] = 0.f;

    const int arow = t >> 1;
    const int acol = (t & 1) * 4;
    constexpr int BTOT = BK * BN / 4;
    const int brow = (t * 4) / BN;
    const int bcol = (t * 4) % BN;

    for (int k0 = 0; k0 < K; k0 += BK) {
        float4 av = make_float4(0.f, 0.f, 0.f, 0.f);
        if (m0 + arow < M) av = *(const float4*)(A + (size_t)(m0 + arow) * K + k0 + acol);
        As[acol + 0][arow] = av.x;
        As[acol + 1][arow] = av.y;
        As[acol + 2][arow] = av.z;
        As[acol + 3][arow] = av.w;
        if (t < BTOT) {
            float4 bv = *(const float4*)(B + (size_t)(k0 + brow) * N + n0 + bcol);
            *(float4*)&Bs[brow][bcol] = bv;
        }
        __syncthreads();
#pragma unroll
        for (int kk = 0; kk < BK; kk++) {
            float a[TM], b[TN];
#pragma unroll
            for (int i = 0; i < TM; i += 4) *(float4*)&a[i] = *(const float4*)&As[kk][ty * TM + i];
#pragma unroll
            for (int j = 0; j < TN; j += 4) *(float4*)&b[j] = *(const float4*)&Bs[kk][tx * TN + j];
#pragma unroll
            for (int i = 0; i < TM; i++)
#pragma unroll
                for (int j = 0; j < TN; j++) acc[i][j] = fmaf(a[i], b[j], acc[i][j]);
        }
        __syncthreads();
    }
#pragma unroll
    for (int i = 0; i < TM; i++) {
        int row = m0 + ty * TM + i;
        if (row >= M) continue;
        if (HALFOUT) {
            __half hv[TN];
#pragma unroll
            for (int j = 0; j < TN; j++) hv[j] = __float2half(acc[i][j]);
            __half* Ch = (__half*)Cv;
            if (TN == 8) {
                *(uint4*)(Ch + (size_t)row * N + n0 + tx * TN) = *(uint4*)hv;
            } else {
#pragma unroll
                for (int j = 0; j < TN; j++) Ch[(size_t)row * N + n0 + tx * TN + j] = hv[j];
            }
        } else {
            float* C = (float*)Cv;
#pragma unroll
            for (int j = 0; j < TN; j++) {
                int col = n0 + tx * TN + j;
                float v = acc[i][j] + bias[col];
                if (act) v = fmaxf(v, 0.f);
                C[(size_t)row * N + col] = v;
            }
        }
    }
}

// ---------------- CSR build --------------------------------------------------
__global__ void hist_kernel(const int* __restrict__ dst, int* __restrict__ deg) {
    int e = blockIdx.x * blockDim.x + threadIdx.x;
    if (e < NE) atomicAdd(&deg[dst[e]], 1);
}

__global__ void scan_block_sums(const int* __restrict__ deg, int* __restrict__ bsum) {
    __shared__ int sh[SB];
    int i = blockIdx.x * SB + threadIdx.x;
    sh[threadIdx.x] = (i < NN) ? deg[i] : 0;
    __syncthreads();
    for (int o = SB / 2; o > 0; o >>= 1) {
        if (threadIdx.x < o) sh[threadIdx.x] += sh[threadIdx.x + o];
        __syncthreads();
    }
    if (threadIdx.x == 0) bsum[blockIdx.x] = sh[0];
}

__global__ void scan_offsets(const int* __restrict__ bsum, int* __restrict__ boff, int nb) {
    __shared__ int sh[SB];
    int t = threadIdx.x;
    int mine = (t < nb) ? bsum[t] : 0;
    sh[t] = mine;
    __syncthreads();
    for (int o = 1; o < SB; o <<= 1) {
        int v = (t >= o) ? sh[t - o] : 0;
        __syncthreads();
        sh[t] += v;
        __syncthreads();
    }
    if (t < nb) boff[t] = sh[t] - mine;
}

__global__ void scan_final(const int* __restrict__ deg, const int* __restrict__ boff,
                           int* __restrict__ rowptr, int* __restrict__ cursor) {
    __shared__ int sh[SB];
    int t = threadIdx.x;
    int i = blockIdx.x * SB + t;
    int d = (i < NN) ? deg[i] : 0;
    sh[t] = d;
    __syncthreads();
    for (int o = 1; o < SB; o <<= 1) {
        int v = (t >= o) ? sh[t - o] : 0;
        __syncthreads();
        sh[t] += v;
        __syncthreads();
    }
    int excl = boff[blockIdx.x] + sh[t] - d;
    if (i < NN) {
        rowptr[i] = excl;
        cursor[i] = excl;
        if (i == NN - 1) rowptr[NN] = excl + d;
    }
}

__global__ void scatter_kernel(const int* __restrict__ dst, int* __restrict__ cursor,
                               int* __restrict__ eidx) {
    int e = blockIdx.x * blockDim.x + threadIdx.x;
    if (e < NE) {
        int p = atomicAdd(&cursor[dst[e]], 1);
        eidx[p] = e;
    }
}

// permute src + edge_attr into CSR order
__global__ void perm_kernel(const int* __restrict__ eidx, const int* __restrict__ src,
                            const float* __restrict__ ea, int* __restrict__ src_perm,
                            float* __restrict__ ea_perm) {
    int k = blockIdx.x * blockDim.x + threadIdx.x;
    if (k >= NE) return;
    int e = eidx[k];
    src_perm[k] = src[e];
    const float4* from = (const float4*)(ea + (size_t)e * 16);
    float4* to = (float4*)(ea_perm + (size_t)k * 16);
    to[0] = from[0]; to[1] = from[1]; to[2] = from[2]; to[3] = from[3];
}

// ---------------- fused GATv2: logits + online softmax + aggregate -----------
// warp per destination node, channel-parallel (lane handles c = j*32+lane).
template<int MEAN>
__global__ void gat_fused(const float* __restrict__ xl, const float* __restrict__ xr,
                          const __half* __restrict__ em, const int* __restrict__ src_perm,
                          const int* __restrict__ rowptr, const float* __restrict__ att,
                          float* __restrict__ out) {
    const int lane = threadIdx.x & 31;
    const int d = blockIdx.x * (blockDim.x >> 5) + (threadIdx.x >> 5);
    if (d >= NN) return;
    const int start = rowptr[d];
    const int deg = rowptr[d + 1] - start;

    float attv[8], xrv[8];
#pragma unroll
    for (int j = 0; j < 8; j++) attv[j] = att[j * 32 + lane];
    if (deg > 0) {
#pragma unroll
        for (int j = 0; j < 8; j++) xrv[j] = xr[(size_t)d * 256 + j * 32 + lane];
    }

    float m0 = -INFINITY, m1 = -INFINITY, m2 = -INFINITY, m3 = -INFINITY;
    float s0 = 0.f, s1 = 0.f, s2 = 0.f, s3 = 0.f;
    float acc[8];
#pragma unroll
    for (int j = 0; j < 8; j++) acc[j] = 0.f;

    for (int k = 0; k < deg; k++) {
        const int idx = start + k;
        const int sn = src_perm[idx];              // uniform -> broadcast load
        const float* xls = xl + (size_t)sn * 256;
        const __half* emr = em + (size_t)idx * 256;
        float xlv[8];
        float hp0 = 0.f, hp1 = 0.f, hp2 = 0.f, hp3 = 0.f;
#pragma unroll
        for (int j = 0; j < 8; j++) {
            const int c = j * 32 + lane;
            xlv[j] = xls[c];
            float z = xlv[j] + xrv[j] + __half2float(emr[c]);
            z = (z > 0.f) ? z : 0.2f * z;
            float p = z * attv[j];
            if (j < 2) hp0 += p; else if (j < 4) hp1 += p; else if (j < 6) hp2 += p; else hp3 += p;
        }
#pragma unroll
        for (int o = 16; o > 0; o >>= 1) {
            hp0 += __shfl_xor_sync(0xffffffffu, hp0, o);
            hp1 += __shfl_xor_sync(0xffffffffu, hp1, o);
            hp2 += __shfl_xor_sync(0xffffffffu, hp2, o);
            hp3 += __shfl_xor_sync(0xffffffffu, hp3, o);
        }
        // online softmax update per head
        {
            float mn = fmaxf(m0, hp0);
            float cs = __expf(m0 - mn), w = __expf(hp0 - mn);
            s0 = s0 * cs + w;
            acc[0] = acc[0] * cs + w * xlv[0];
            acc[1] = acc[1] * cs + w * xlv[1];
            m0 = mn;
        }
        {
            float mn = fmaxf(m1, hp1);
            float cs = __expf(m1 - mn), w = __expf(hp1 - mn);
            s1 = s1 * cs + w;
            acc[2] = acc[2] * cs + w * xlv[2];
            acc[3] = acc[3] * cs + w * xlv[3];
            m1 = mn;
        }
        {
            float mn = fmaxf(m2, hp2);
            float cs = __expf(m2 - mn), w = __expf(hp2 - mn);
            s2 = s2 * cs + w;
            acc[4] = acc[4] * cs + w * xlv[4];
            acc[5] = acc[5] * cs + w * xlv[5];
            m2 = mn;
        }
        {
            float mn = fmaxf(m3, hp3);
            float cs = __expf(m3 - mn), w = __expf(hp3 - mn);
            s3 = s3 * cs + w;
            acc[6] = acc[6] * cs + w * xlv[6];
            acc[7] = acc[7] * cs + w * xlv[7];
            m3 = mn;
        }
    }
    float i0 = 1.f / (s0 + 1e-16f), i1 = 1.f / (s1 + 1e-16f);
    float i2 = 1.f / (s2 + 1e-16f), i3 = 1.f / (s3 + 1e-16f);
    if (MEAN) {
        out[(size_t)d * 64 + lane] =
            0.25f * (acc[0] * i0 + acc[2] * i1 + acc[4] * i2 + acc[6] * i3);
        out[(size_t)d * 64 + 32 + lane] =
            0.25f * (acc[1] * i0 + acc[3] * i1 + acc[5] * i2 + acc[7] * i3);
    } else {
        float inv[4] = {i0, i1, i2, i3};
#pragma unroll
        for (int j = 0; j < 8; j++)
            out[(size_t)d * 256 + j * 32 + lane] = acc[j] * inv[j >> 1];
    }
}

// ---------------- batch norm --------------------------------------------------
__global__ void bn_stats(const float* __restrict__ h, double* __restrict__ sum,
                         double* __restrict__ sumsq, int N, int Cf, int rowsPerBlock) {
    const int t = threadIdx.x;
    const int col = t % Cf;
    const int rpb = blockDim.x / Cf;
    int r0 = blockIdx.x * rowsPerBlock;
    int rend = min(N, r0 + rowsPerBlock);
    double s = 0.0, ss = 0.0;
    for (int r = r0 + t / Cf; r < rend; r += rpb) {
        double v = (double)h[(size_t)r * Cf + col];
        s += v;
        ss += v * v;
    }
    atomicAdd(&sum[col], s);
    atomicAdd(&sumsq[col], ss);
}

__global__ void bn_apply(float* __restrict__ h, const double* __restrict__ sum,
                         const double* __restrict__ sumsq, const float* __restrict__ gamma,
                         const float* __restrict__ beta, int N, int Cf, int doRelu) {
    size_t i = (size_t)blockIdx.x * blockDim.x + threadIdx.x;
    if (i >= (size_t)N * Cf) return;
    int col = (int)(i % Cf);
    float mu = (float)(sum[col] / N);
    float var = (float)(sumsq[col] / N) - mu * mu;
    float v = gamma[col] * (h[i] - mu) * rsqrtf(var + BN_EPS) + beta[col];
    if (doRelu) v = fmaxf(v, 0.f);
    h[i] = v;
}

// ---------------- pool + MLP ---------------------------------------------------
__global__ void pool_kernel(const float* __restrict__ h, const int* __restrict__ batch,
                            float* __restrict__ pooled, float* __restrict__ cnt, int N) {
    int i = blockIdx.x * blockDim.x + threadIdx.x;
    if (i >= N * 64) return;
    int n = i >> 6, c = i & 63;
    int b = batch[n];
    atomicAdd(&pooled[b * 64 + c], h[i]);
    if (c == 0) atomicAdd(&cnt[b], 1.f);
}

__global__ void mlp_kernel(const float* __restrict__ pooled, const float* __restrict__ cnt,
                           const float* __restrict__ Wm1, const float* __restrict__ bm1,
                           const float* __restrict__ Wm2, const float* __restrict__ bm2,
                           const float* __restrict__ Wm3, const float* __restrict__ bm3,
                           float* __restrict__ out) {
    __shared__ float w1[64 * 32], w2[32 * 16], w3[16];
    int t = threadIdx.x;
    for (int i = t; i < 64 * 32; i += 256) w1[i] = Wm1[i];
    for (int i = t; i < 32 * 16; i += 256) w2[i] = Wm2[i];
    if (t < 16) w3[t] = Wm3[t];
    __syncthreads();
    float p[64];
    float c = fmaxf(cnt[t], 1.f);
#pragma unroll
    for (int f = 0; f < 64; f++) p[f] = pooled[t * 64 + f] / c;
    float z1[32];
#pragma unroll
    for (int j = 0; j < 32; j++) {
        float v = bm1[j];
#pragma unroll
        for (int f = 0; f < 64; f++) v = fmaf(p[f], w1[f * 32 + j], v);
        z1[j] = fmaxf(v, 0.f);
    }
    float z2[16];
#pragma unroll
    for (int j = 0; j < 16; j++) {
        float v = bm2[j];
#pragma unroll
        for (int f = 0; f < 32; f++) v = fmaf(z1[f], w2[f * 16 + j], v);
        z2[j] = fmaxf(v, 0.f);
    }
    float o = bm3[0];
#pragma unroll
    for (int f = 0; f < 16; f++) o = fmaf(z2[f], w3[f], o);
    out[t] = o;
}

// ---------------- launch --------------------------------------------------------
extern "C" void kernel_launch(void* const* d_in, const int* in_sizes, int n_in,
                              void* d_out, int out_size) {
    const float* f[28];
    int nf = 0, idx_ei = -1, idx_b = -1;
    for (int i = 0; i < n_in; i++) {
        if (idx_ei < 0 && in_sizes[i] == 2 * NE) { idx_ei = i; continue; }
        if (idx_b < 0 && in_sizes[i] == NN) { idx_b = i; continue; }
        if (nf < 28) f[nf++] = (const float*)d_in[i];
    }
    const float *x = f[0], *edge_attr = f[1], *W_in = f[2], *b_in = f[3];
    const float *Wl0 = f[4], *bl0 = f[5], *Wr0 = f[6], *br0 = f[7], *We0 = f[8];
    const float *att0 = f[9] /* bias0=f[10] cancels in BN */, *g0 = f[11], *beta0 = f[12];
    const float *Wl1 = f[13], *bl1 = f[14], *Wr1 = f[15], *br1 = f[16], *We1 = f[17];
    const float *att1 = f[18] /* bias1=f[19] cancels in BN */, *g1 = f[20], *beta1 = f[21];
    const float *Wm1 = f[22], *bm1 = f[23], *Wm2 = f[24], *bm2 = f[25], *Wm3 = f[26], *bm3 = f[27];
    const int* edge_index = (const int*)d_in[idx_ei];
    const int* src = edge_index;
    const int* dst = edge_index + NE;
    const int* batch = (const int*)d_in[idx_b];
    float* out = (float*)d_out;

    void *p_h0, *p_xl, *p_xr, *p_agg, *p_em, *p_eap, *p_sp, *p_deg, *p_rowptr, *p_cursor,
         *p_eidx, *p_bsum, *p_boff, *p_bns, *p_bnss, *p_pool, *p_cnt;
    cudaGetSymbolAddress(&p_h0, g_h0);
    cudaGetSymbolAddress(&p_xl, g_xl);
    cudaGetSymbolAddress(&p_xr, g_xr);
    cudaGetSymbolAddress(&p_agg, g_agg);
    cudaGetSymbolAddress(&p_em, g_em);
    cudaGetSymbolAddress(&p_eap, g_ea_perm);
    cudaGetSymbolAddress(&p_sp, g_src_perm);
    cudaGetSymbolAddress(&p_deg, g_deg);
    cudaGetSymbolAddress(&p_rowptr, g_rowptr);
    cudaGetSymbolAddress(&p_cursor, g_cursor);
    cudaGetSymbolAddress(&p_eidx, g_eidx);
    cudaGetSymbolAddress(&p_bsum, g_bsum);
    cudaGetSymbolAddress(&p_boff, g_boff);
    cudaGetSymbolAddress(&p_bns, g_bns);
    cudaGetSymbolAddress(&p_bnss, g_bnss);
    cudaGetSymbolAddress(&p_pool, g_pool);
    cudaGetSymbolAddress(&p_cnt, g_cnt);
    float* h0 = (float*)p_h0;
    float* xl = (float*)p_xl;
    float* xr = (float*)p_xr;
    float* agg = (float*)p_agg;
    __half* em = (__half*)p_em;
    float* ea_perm = (float*)p_eap;
    int* src_perm = (int*)p_sp;
    int* deg = (int*)p_deg;
    int* rowptr = (int*)p_rowptr;
    int* cursor = (int*)p_cursor;
    int* eidx = (int*)p_eidx;
    int* bsum = (int*)p_bsum;
    int* boff = (int*)p_boff;
    double* bns = (double*)p_bns;
    double* bnss = (double*)p_bnss;
    float* pool = (float*)p_pool;
    float* cnt = (float*)p_cnt;

    const int NB = (NN + 7) / 8;
    const int ROWS = 128;
    const int bnBlocks = (NN + ROWS - 1) / ROWS;

    // ---- CSR build + permutation (dst shared by both layers)
    cudaMemsetAsync(deg, 0, NN * sizeof(int));
    hist_kernel<<<(NE + 255) / 256, 256>>>(dst, deg);
    scan_block_sums<<<SNB, SB>>>(deg, bsum);
    scan_offsets<<<1, SB>>>(bsum, boff, SNB);
    scan_final<<<SNB, SB>>>(deg, boff, rowptr, cursor);
    scatter_kernel<<<(NE + 255) / 256, 256>>>(dst, cursor, eidx);
    perm_kernel<<<(NE + 255) / 256, 256>>>(eidx, src, edge_attr, src_perm, ea_perm);

    // ---- input projection: h0 = relu(x@W_in + b_in)
    {
        dim3 g(1, (NN + 127) / 128);
        gemm_kernel<128, 64, 8, 8, 4, false><<<g, 256>>>(x, W_in, b_in, h0, NN, 64, 64, 1);
    }

    // ---- GATv2 layer 0
    {
        dim3 g(2, (NN + 127) / 128);
        gemm_kernel<128, 128, 8, 8, 8, false><<<g, 256>>>(h0, Wl0, bl0, xl, NN, 256, 64, 0);
        gemm_kernel<128, 128, 8, 8, 8, false><<<g, 256>>>(h0, Wr0, br0, xr, NN, 256, 64, 0);
        dim3 ge(2, (NE + 127) / 128);
        gemm_kernel<128, 128, 8, 8, 8, true><<<ge, 256>>>(ea_perm, We0, nullptr, em, NE, 256, 16, 0);
    }
    gat_fused<0><<<NB, 256>>>(xl, xr, em, src_perm, rowptr, att0, agg);
    cudaMemsetAsync(bns, 0, 256 * sizeof(double));
    cudaMemsetAsync(bnss, 0, 256 * sizeof(double));
    bn_stats<<<bnBlocks, 256>>>(agg, bns, bnss, NN, 256, ROWS);
    bn_apply<<<(NN * 256 + 255) / 256, 256>>>(agg, bns, bnss, g0, beta0, NN, 256, 1);

    // ---- GATv2 layer 1
    {
        dim3 g(2, (NN + 127) / 128);
        gemm_kernel<128, 128, 8, 8, 8, false><<<g, 256>>>(agg, Wl1, bl1, xl, NN, 256, 256, 0);
        gemm_kernel<128, 128, 8, 8, 8, false><<<g, 256>>>(agg, Wr1, br1, xr, NN, 256, 256, 0);
        dim3 ge(2, (NE + 127) / 128);
        gemm_kernel<128, 128, 8, 8, 8, true><<<ge, 256>>>(ea_perm, We1, nullptr, em, NE, 256, 16, 0);
    }
    gat_fused<1><<<NB, 256>>>(xl, xr, em, src_perm, rowptr, att1, h0);
    cudaMemsetAsync(bns, 0, 256 * sizeof(double));
    cudaMemsetAsync(bnss, 0, 256 * sizeof(double));
    bn_stats<<<bnBlocks, 256>>>(h0, bns, bnss, NN, 64, ROWS);
    bn_apply<<<(NN * 64 + 255) / 256, 256>>>(h0, bns, bnss, g1, beta1, NN, 64, 0);

    // ---- global mean pool + MLP head
    cudaMemsetAsync(pool, 0, NG * 64 * sizeof(float));
    cudaMemsetAsync(cnt, 0, NG * sizeof(float));
    pool_kernel<<<(NN * 64 + 255) / 256, 256>>>(h0, batch, pool, cnt, NN);
    mlp_kernel<<<1, 256>>>(pool, cnt, Wm1, bm1, Wm2, bm2, Wm3, bm3, out);
}